// round 7
// baseline (speedup 1.0000x reference)
#include <cuda_runtime.h>
#include <cstdint>

#define N_USERS 100000
#define N_ITEMS 50000
#define N_NODESC 150000
#define NNZC 2400000
#define DIM 64
#define BATCHC 4096
#define HALFC 4800000u
#define NPAIR 75000
#define EPSC 0.1f
#define INV_TEMP 5.0f

// ---------------- static device scratch (allocation-free) ----------------
__device__ float  g_ego[N_NODESC * DIM];
__device__ float  g_e1 [N_NODESC * DIM];
__device__ float  g_e2 [N_NODESC * DIM];
__device__ float4 g_y1 [N_NODESC * 32];   // interleaved: (v1x,v1y,v2x,v2y) at [row*32+lane]
__device__ float4 g_y2 [N_NODESC * 32];
__device__ int2   g_cv[NNZC];
__device__ int    g_rowptr[N_NODESC + 1];
__device__ int    g_cursor[N_NODESC];
__device__ int    g_counts[N_NODESC];
__device__ int    g_blocksums[256];
__device__ int    g_flags[N_NODESC];
__device__ int    g_uidx[BATCHC];
__device__ int    g_iidx[BATCHC];
__device__ int    g_ucnt;
__device__ int    g_icnt;
__device__ float  g_V1u[BATCHC * DIM], g_V2u[BATCHC * DIM];
__device__ float  g_V1i[BATCHC * DIM], g_V2i[BATCHC * DIM];
__device__ float  g_posU[BATCHC], g_posI[BATCHC];
__device__ float  g_S[2 * BATCHC];
__device__ float  g_acc[8];               // 0 rec, 1 ssu, 2 ssp, 3 nceU, 4 nceI

// ---------------- threefry-2x32 (exact JAX schedule) ----------------
__host__ __device__ __forceinline__ unsigned rl32(unsigned x, int r) {
    return (x << r) | (x >> (32 - r));
}
__host__ __device__ __forceinline__ void tf2x32(unsigned k0, unsigned k1,
                                                unsigned x0, unsigned x1,
                                                unsigned& o0, unsigned& o1) {
    unsigned k2 = k0 ^ k1 ^ 0x1BD11BDAu;
    x0 += k0; x1 += k1;
#define TFR(r) { x0 += x1; x1 = rl32(x1, r); x1 ^= x0; }
    TFR(13) TFR(15) TFR(26) TFR(6)
    x0 += k1; x1 += k2 + 1u;
    TFR(17) TFR(29) TFR(16) TFR(24)
    x0 += k2; x1 += k0 + 2u;
    TFR(13) TFR(15) TFR(26) TFR(6)
    x0 += k0; x1 += k1 + 3u;
    TFR(17) TFR(29) TFR(16) TFR(24)
    x0 += k1; x1 += k2 + 4u;
    TFR(13) TFR(15) TFR(26) TFR(6)
    x0 += k2; x1 += k0 + 5u;
#undef TFR
    o0 = x0; o1 = x1;
}
__device__ __forceinline__ float u32_to_unit(unsigned b) {
    return __uint_as_float((b >> 9) | 0x3f800000u) - 1.0f;
}
__device__ __forceinline__ float wredsum(float v) {
#pragma unroll
    for (int o = 16; o; o >>= 1) v += __shfl_xor_sync(0xffffffffu, v, o);
    return v;
}
__device__ __forceinline__ float sgn(float x) {
    return (x > 0.f) ? 1.f : ((x < 0.f) ? -1.f : 0.f);
}

// per-row noise: row's values at cols (2*lane, 2*lane+1), exact JAX iota pairing.
// rows r and r+NPAIR share threefry blocks; half selects out0/out1.
__device__ __forceinline__ void row_noise(int row, int lane, unsigned k0, unsigned k1,
                                          float& nx, float& ny, float& sc) {
    int half = (row >= NPAIR);
    unsigned base = (unsigned)(half ? row - NPAIR : row) * 64u + (unsigned)(lane * 2);
    unsigned a0, a1, b0, b1;
    tf2x32(k0, k1, base, base + HALFC, a0, a1);
    tf2x32(k0, k1, base + 1u, base + 1u + HALFC, b0, b1);
    nx = u32_to_unit(half ? a1 : a0);
    ny = u32_to_unit(half ? b1 : b0);
    sc = EPSC * rsqrtf(wredsum(nx * nx + ny * ny));
}

// warp computes one CSR row (float2 source) at cols (2*lane, 2*lane+1); 4-wide MLP
__device__ __forceinline__ float2 csr_row(const float* __restrict__ x, int row, int lane) {
    int s = g_rowptr[row], e = g_rowptr[row + 1];
    float ax = 0.f, ay = 0.f, bx = 0.f, by = 0.f;
    float cx = 0.f, cy = 0.f, dx = 0.f, dy = 0.f;
    int i = s;
    for (; i + 3 < e; i += 4) {
        int2 c0 = g_cv[i], c1 = g_cv[i + 1], c2 = g_cv[i + 2], c3 = g_cv[i + 3];
        float2 p0 = ((const float2*)(x + (c0.x << 6)))[lane];
        float2 p1 = ((const float2*)(x + (c1.x << 6)))[lane];
        float2 p2 = ((const float2*)(x + (c2.x << 6)))[lane];
        float2 p3 = ((const float2*)(x + (c3.x << 6)))[lane];
        float v0 = __int_as_float(c0.y), v1 = __int_as_float(c1.y);
        float v2 = __int_as_float(c2.y), v3 = __int_as_float(c3.y);
        ax = fmaf(v0, p0.x, ax); ay = fmaf(v0, p0.y, ay);
        bx = fmaf(v1, p1.x, bx); by = fmaf(v1, p1.y, by);
        cx = fmaf(v2, p2.x, cx); cy = fmaf(v2, p2.y, cy);
        dx = fmaf(v3, p3.x, dx); dy = fmaf(v3, p3.y, dy);
    }
    for (; i < e; i++) {
        int2 c0 = g_cv[i];
        float2 p0 = ((const float2*)(x + (c0.x << 6)))[lane];
        float v0 = __int_as_float(c0.y);
        ax = fmaf(v0, p0.x, ax); ay = fmaf(v0, p0.y, ay);
    }
    return make_float2((ax + bx) + (cx + dx), (ay + by) + (cy + dy));
}

// warp computes one CSR row over interleaved float4 source; 4-wide MLP
__device__ __forceinline__ float4 csr_row4(const float4* __restrict__ x, int row, int lane) {
    int s = g_rowptr[row], e = g_rowptr[row + 1];
    float ax = 0.f, ay = 0.f, az = 0.f, aw = 0.f;
    float bx = 0.f, by = 0.f, bz = 0.f, bw = 0.f;
    int i = s;
    for (; i + 3 < e; i += 4) {
        int2 c0 = g_cv[i], c1 = g_cv[i + 1], c2 = g_cv[i + 2], c3 = g_cv[i + 3];
        float4 p0 = x[(c0.x << 5) + lane];
        float4 p1 = x[(c1.x << 5) + lane];
        float4 p2 = x[(c2.x << 5) + lane];
        float4 p3 = x[(c3.x << 5) + lane];
        float v0 = __int_as_float(c0.y), v1 = __int_as_float(c1.y);
        float v2 = __int_as_float(c2.y), v3 = __int_as_float(c3.y);
        ax = fmaf(v0, p0.x, ax); ay = fmaf(v0, p0.y, ay);
        az = fmaf(v0, p0.z, az); aw = fmaf(v0, p0.w, aw);
        bx = fmaf(v1, p1.x, bx); by = fmaf(v1, p1.y, by);
        bz = fmaf(v1, p1.z, bz); bw = fmaf(v1, p1.w, bw);
        ax = fmaf(v2, p2.x, ax); ay = fmaf(v2, p2.y, ay);
        az = fmaf(v2, p2.z, az); aw = fmaf(v2, p2.w, aw);
        bx = fmaf(v3, p3.x, bx); by = fmaf(v3, p3.y, by);
        bz = fmaf(v3, p3.z, bz); bw = fmaf(v3, p3.w, bw);
    }
    for (; i < e; i++) {
        int2 c0 = g_cv[i];
        float4 p0 = x[(c0.x << 5) + lane];
        float v0 = __int_as_float(c0.y);
        ax = fmaf(v0, p0.x, ax); ay = fmaf(v0, p0.y, ay);
        az = fmaf(v0, p0.z, az); aw = fmaf(v0, p0.w, aw);
    }
    return make_float4(ax + bx, ay + by, az + bz, aw + bw);
}

// fused: one CSR pass computing BOTH e2 (from g_e1, float2) and y2 (from g_y1, float4)
__device__ __forceinline__ void csr_row6(int row, int lane, float2& oe, float4& oy) {
    int s = g_rowptr[row], e = g_rowptr[row + 1];
    float ex0 = 0.f, ey0 = 0.f, ex1 = 0.f, ey1 = 0.f;
    float yx0 = 0.f, yy0 = 0.f, yz0 = 0.f, yw0 = 0.f;
    float yx1 = 0.f, yy1 = 0.f, yz1 = 0.f, yw1 = 0.f;
    int i = s;
    for (; i + 3 < e; i += 4) {
        int2 c0 = g_cv[i], c1 = g_cv[i + 1], c2 = g_cv[i + 2], c3 = g_cv[i + 3];
        float2 q0 = ((const float2*)(g_e1 + (c0.x << 6)))[lane];
        float2 q1 = ((const float2*)(g_e1 + (c1.x << 6)))[lane];
        float2 q2 = ((const float2*)(g_e1 + (c2.x << 6)))[lane];
        float2 q3 = ((const float2*)(g_e1 + (c3.x << 6)))[lane];
        float4 p0 = g_y1[(c0.x << 5) + lane];
        float4 p1 = g_y1[(c1.x << 5) + lane];
        float4 p2 = g_y1[(c2.x << 5) + lane];
        float4 p3 = g_y1[(c3.x << 5) + lane];
        float v0 = __int_as_float(c0.y), v1 = __int_as_float(c1.y);
        float v2 = __int_as_float(c2.y), v3 = __int_as_float(c3.y);
        ex0 = fmaf(v0, q0.x, ex0); ey0 = fmaf(v0, q0.y, ey0);
        ex1 = fmaf(v1, q1.x, ex1); ey1 = fmaf(v1, q1.y, ey1);
        ex0 = fmaf(v2, q2.x, ex0); ey0 = fmaf(v2, q2.y, ey0);
        ex1 = fmaf(v3, q3.x, ex1); ey1 = fmaf(v3, q3.y, ey1);
        yx0 = fmaf(v0, p0.x, yx0); yy0 = fmaf(v0, p0.y, yy0);
        yz0 = fmaf(v0, p0.z, yz0); yw0 = fmaf(v0, p0.w, yw0);
        yx1 = fmaf(v1, p1.x, yx1); yy1 = fmaf(v1, p1.y, yy1);
        yz1 = fmaf(v1, p1.z, yz1); yw1 = fmaf(v1, p1.w, yw1);
        yx0 = fmaf(v2, p2.x, yx0); yy0 = fmaf(v2, p2.y, yy0);
        yz0 = fmaf(v2, p2.z, yz0); yw0 = fmaf(v2, p2.w, yw0);
        yx1 = fmaf(v3, p3.x, yx1); yy1 = fmaf(v3, p3.y, yy1);
        yz1 = fmaf(v3, p3.z, yz1); yw1 = fmaf(v3, p3.w, yw1);
    }
    for (; i < e; i++) {
        int2 c0 = g_cv[i];
        float2 q0 = ((const float2*)(g_e1 + (c0.x << 6)))[lane];
        float4 p0 = g_y1[(c0.x << 5) + lane];
        float v0 = __int_as_float(c0.y);
        ex0 = fmaf(v0, q0.x, ex0); ey0 = fmaf(v0, q0.y, ey0);
        yx0 = fmaf(v0, p0.x, yx0); yy0 = fmaf(v0, p0.y, yy0);
        yz0 = fmaf(v0, p0.z, yz0); yw0 = fmaf(v0, p0.w, yw0);
    }
    oe = make_float2(ex0 + ex1, ey0 + ey1);
    oy = make_float4(yx0 + yx1, yy0 + yy1, yz0 + yz1, yw0 + yw1);
}

// ---------------- setup ----------------
__global__ void k_init(const float* __restrict__ ue, const float* __restrict__ ie) {
    int i = blockIdx.x * blockDim.x + threadIdx.x;
    if (i < N_NODESC * DIM)
        g_ego[i] = (i < N_USERS * DIM) ? ue[i] : ie[i - N_USERS * DIM];
    if (i < N_NODESC) { g_flags[i] = 0; g_counts[i] = 0; }
    if (i < 2 * BATCHC) g_S[i] = 0.f;
    if (i < 8) g_acc[i] = 0.f;
    if (i == 0) { g_ucnt = 0; g_icnt = 0; }
}
__global__ void k_hist(const int* __restrict__ rows) {
    int i = blockIdx.x * blockDim.x + threadIdx.x;
    if (i < NNZC) atomicAdd(&g_counts[rows[i]], 1);
}
__global__ void k_scan1() {
    __shared__ int sh[1024];
    int g = blockIdx.x * 1024 + threadIdx.x;
    int v = (g < N_NODESC) ? g_counts[g] : 0;
    sh[threadIdx.x] = v;
    __syncthreads();
    for (int off = 1; off < 1024; off <<= 1) {
        int t = (threadIdx.x >= off) ? sh[threadIdx.x - off] : 0;
        __syncthreads();
        sh[threadIdx.x] += t;
        __syncthreads();
    }
    if (g < N_NODESC) g_rowptr[g] = sh[threadIdx.x] - v;
    if (threadIdx.x == 1023) g_blocksums[blockIdx.x] = sh[1023];
}
__global__ void k_scan2(int nblocks) {
    if (threadIdx.x == 0) {
        int acc = 0;
        for (int b = 0; b < nblocks; b++) { int t = g_blocksums[b]; g_blocksums[b] = acc; acc += t; }
        g_rowptr[N_NODESC] = acc;
    }
}
__global__ void k_scan3() {
    int g = blockIdx.x * blockDim.x + threadIdx.x;
    if (g < N_NODESC) {
        int v = g_rowptr[g] + g_blocksums[g >> 10];
        g_rowptr[g] = v;
        g_cursor[g] = v;
    }
}
__global__ void k_fill(const int* __restrict__ rows, const int* __restrict__ cols,
                       const float* __restrict__ vals) {
    int i = blockIdx.x * blockDim.x + threadIdx.x;
    if (i < NNZC) {
        int p = atomicAdd(&g_cursor[rows[i]], 1);
        g_cv[p] = make_int2(cols[i], __float_as_int(vals[i]));
    }
}

// ---------------- e1 = A*ego (warp per row) + fused layer-1 noise, both views ----------------
__global__ void __launch_bounds__(256) k_spmm_e1_noise(unsigned f10, unsigned f11,
                                                       unsigned f20, unsigned f21) {
    int w = (blockIdx.x * blockDim.x + threadIdx.x) >> 5;
    int lane = threadIdx.x & 31;
    if (w >= N_NODESC) return;
    float2 ea = csr_row(g_ego, w, lane);
    ((float2*)(g_e1 + (w << 6)))[lane] = ea;
    float4 o;
    float nx, ny, sc;
    row_noise(w, lane, f10, f11, nx, ny, sc);
    o.x = ea.x + sgn(ea.x) * nx * sc;
    o.y = ea.y + sgn(ea.y) * ny * sc;
    row_noise(w, lane, f20, f21, nx, ny, sc);
    o.z = ea.x + sgn(ea.x) * nx * sc;
    o.w = ea.y + sgn(ea.y) * ny * sc;
    g_y1[(w << 5) + lane] = o;
}

// ---------------- fused layer-2: e2 = A*e1 AND y2 = A*y1 (+noise), one CSR pass ----------------
__global__ void __launch_bounds__(256) k_spmm_l2(unsigned f10, unsigned f11,
                                                 unsigned f20, unsigned f21) {
    int w = (blockIdx.x * blockDim.x + threadIdx.x) >> 5;
    int lane = threadIdx.x & 31;
    if (w >= N_NODESC) return;
    float2 oe;
    float4 oy;
    csr_row6(w, lane, oe, oy);
    ((float2*)(g_e2 + (w << 6)))[lane] = oe;
    float nx, ny, sc;
    row_noise(w, lane, f10, f11, nx, ny, sc);
    oy.x += sgn(oy.x) * nx * sc;
    oy.y += sgn(oy.y) * ny * sc;
    row_noise(w, lane, f20, f21, nx, ny, sc);
    oy.z += sgn(oy.z) * nx * sc;
    oy.w += sgn(oy.w) * ny * sc;
    g_y2[(w << 5) + lane] = oy;
}

// ---------------- BPR: warp per batch entry, layer-3 rows on the fly ----------------
__global__ void __launch_bounds__(256) k_bpr(const int* __restrict__ ul,
                                             const int* __restrict__ pl,
                                             const int* __restrict__ nl) {
    int w = (blockIdx.x * blockDim.x + threadIdx.x) >> 5;
    int lane = threadIdx.x & 31;
    if (w >= BATCHC) return;
    const float third = 1.f / 3.f;
    int ru = ul[w];
    int rp = N_USERS + pl[w];
    int rn = N_USERS + nl[w];
    float2 u3 = csr_row(g_e2, ru, lane);
    float2 p3 = csr_row(g_e2, rp, lane);
    float2 n3 = csr_row(g_e2, rn, lane);
    float2 u1 = ((const float2*)(g_e1 + (ru << 6)))[lane];
    float2 u2 = ((const float2*)(g_e2 + (ru << 6)))[lane];
    float2 p1 = ((const float2*)(g_e1 + (rp << 6)))[lane];
    float2 p2 = ((const float2*)(g_e2 + (rp << 6)))[lane];
    float2 n1 = ((const float2*)(g_e1 + (rn << 6)))[lane];
    float2 n2 = ((const float2*)(g_e2 + (rn << 6)))[lane];
    float ux = (u1.x + u2.x + u3.x) * third, uy = (u1.y + u2.y + u3.y) * third;
    float px = (p1.x + p2.x + p3.x) * third, py = (p1.y + p2.y + p3.y) * third;
    float nx = (n1.x + n2.x + n3.x) * third, ny = (n1.y + n2.y + n3.y) * third;
    float pos = wredsum(ux * px + uy * py);
    float neg = wredsum(ux * nx + uy * ny);
    float ssu = wredsum(ux * ux + uy * uy);
    float ssp = wredsum(px * px + py * py);
    if (lane == 0) {
        float d = pos - neg;
        float sig = 1.f / (1.f + expf(-d));
        atomicAdd(&g_acc[0], -logf(1e-7f + sig));
        atomicAdd(&g_acc[1], ssu);
        atomicAdd(&g_acc[2], ssp);
    }
}

// ---------------- order-free unique (both lists in one launch) ----------------
__global__ void k_unique2(const int* __restrict__ ul, const int* __restrict__ pl) {
    int i = blockIdx.x * blockDim.x + threadIdx.x;
    if (i >= 2 * BATCHC) return;
    int which = (i >= BATCHC);
    int j = which ? i - BATCHC : i;
    int v = which ? pl[j] : ul[j];
    int fidx = which ? (N_USERS + v) : v;
    if (atomicExch(&g_flags[fidx], 1) == 0) {
        int p = atomicAdd(which ? &g_icnt : &g_ucnt, 1);
        (which ? g_iidx : g_uidx)[p] = v;
    }
}

// ---------------- finalize both views: layer-3 + noise + normalize + pos ----------------
__global__ void __launch_bounds__(256) k_vfinal(unsigned f10, unsigned f11,
                                                unsigned f20, unsigned f21) {
    int w = (blockIdx.x * blockDim.x + threadIdx.x) >> 5;
    int lane = threadIdx.x & 31;
    if (w >= 2 * BATCHC) return;
    int isItem = (w >= BATCHC);
    int j = isItem ? w - BATCHC : w;
    int cnt = isItem ? g_icnt : g_ucnt;
    if (j >= cnt) return;
    int row = isItem ? (N_USERS + g_iidx[j]) : g_uidx[j];
    float4 a3 = csr_row4(g_y2, row, lane);
    float nx, ny, sc;
    row_noise(row, lane, f10, f11, nx, ny, sc);
    a3.x += sgn(a3.x) * nx * sc;
    a3.y += sgn(a3.y) * ny * sc;
    row_noise(row, lane, f20, f21, nx, ny, sc);
    a3.z += sgn(a3.z) * nx * sc;
    a3.w += sgn(a3.w) * ny * sc;
    float4 y1r = g_y1[(row << 5) + lane];
    float4 y2r = g_y2[(row << 5) + lane];
    float s1x = y1r.x + y2r.x + a3.x;
    float s1y = y1r.y + y2r.y + a3.y;
    float inv1 = rsqrtf(wredsum(s1x * s1x + s1y * s1y));
    s1x *= inv1; s1y *= inv1;
    float s2x = y1r.z + y2r.z + a3.z;
    float s2y = y1r.w + y2r.w + a3.w;
    float inv2 = rsqrtf(wredsum(s2x * s2x + s2y * s2y));
    s2x *= inv2; s2y *= inv2;
    float* d1 = isItem ? g_V1i : g_V1u;
    float* d2 = isItem ? g_V2i : g_V2u;
    ((float2*)(d1 + (j << 6)))[lane] = make_float2(s1x, s1y);
    ((float2*)(d2 + (j << 6)))[lane] = make_float2(s2x, s2y);
    float d = wredsum(s2x * s1x + s2y * s1y);
    if (lane == 0) (isItem ? g_posI : g_posU)[j] = d * INV_TEMP;
}

// ---------------- InfoNCE (both halves via grid.z) ----------------
#define NCE_CSPLIT 16
#define NCE_COLS (BATCHC / NCE_CSPLIT)
__global__ void __launch_bounds__(128) k_nce() {
    int which = blockIdx.z;
    const float* __restrict__ V1 = which ? g_V1i : g_V1u;
    const float* __restrict__ V2 = which ? g_V2i : g_V2u;
    float* __restrict__ S = g_S + which * BATCHC;
    int U = which ? g_icnt : g_ucnt;
    int r = blockIdx.x * 128 + threadIdx.x;
    float4 v[16];
    if (r < U) {
        const float4* p = (const float4*)(V1 + (r << 6));
#pragma unroll
        for (int i = 0; i < 16; i++) v[i] = p[i];
    }
    __shared__ float sh[128 * DIM];
    float s = 0.f;
    int cbegin = blockIdx.y * NCE_COLS;
    for (int t = cbegin; t < cbegin + NCE_COLS; t += 128) {
        int cmax = U - t; if (cmax > 128) cmax = 128;
        if (cmax > 0) {
            const float4* src = (const float4*)(V2 + (t << 6));
            float4* d4 = (float4*)sh;
            for (int idx = threadIdx.x; idx < cmax * 16; idx += 128) d4[idx] = src[idx];
        }
        __syncthreads();
        if (r < U && cmax > 0) {
            for (int cc = 0; cc < cmax; cc++) {
                const float4* q = (const float4*)(sh + cc * DIM);
                float d0 = 0.f, d1 = 0.f, d2 = 0.f, d3 = 0.f;
#pragma unroll
                for (int i = 0; i < 16; i += 4) {
                    float4 q0 = q[i], q1 = q[i+1], q2 = q[i+2], q3 = q[i+3];
                    d0 = fmaf(v[i].x, q0.x, fmaf(v[i].y, q0.y, fmaf(v[i].z, q0.z, fmaf(v[i].w, q0.w, d0))));
                    d1 = fmaf(v[i+1].x, q1.x, fmaf(v[i+1].y, q1.y, fmaf(v[i+1].z, q1.z, fmaf(v[i+1].w, q1.w, d1))));
                    d2 = fmaf(v[i+2].x, q2.x, fmaf(v[i+2].y, q2.y, fmaf(v[i+2].z, q2.z, fmaf(v[i+2].w, q2.w, d2))));
                    d3 = fmaf(v[i+3].x, q3.x, fmaf(v[i+3].y, q3.y, fmaf(v[i+3].z, q3.z, fmaf(v[i+3].w, q3.w, d3))));
                }
                float dot = (d0 + d1) + (d2 + d3);
                s += __expf(dot * INV_TEMP - 5.0f);
            }
        }
        __syncthreads();
    }
    if (r < U && s != 0.f) atomicAdd(&S[r], s);
}

__global__ void __launch_bounds__(256) k_ncefin() {
    int i = blockIdx.x * blockDim.x + threadIdx.x;
    int which = (i >= BATCHC);
    int j = i - which * BATCHC;
    int U = which ? g_icnt : g_ucnt;
    float c = 0.f;
    if (i < 2 * BATCHC && j < U)
        c = 5.0f + logf(g_S[i]) - (which ? g_posI[j] : g_posU[j]);
    c = wredsum(c);
    if ((threadIdx.x & 31) == 0 && c != 0.f)
        atomicAdd(&g_acc[3 + which], c);
}

__global__ void k_final(float* out) {
    if (threadIdx.x == 0) {
        float rec = g_acc[0] / (float)BATCHC;
        float reg = 1e-4f * (sqrtf(g_acc[1]) + sqrtf(g_acc[2]));
        float cl = 0.2f * (g_acc[3] / (float)g_ucnt + g_acc[4] / (float)g_icnt);
        out[0] = rec + reg + cl;
        out[1] = cl;
    }
}

// ---------------- launch ----------------
extern "C" void kernel_launch(void* const* d_in, const int* in_sizes, int n_in,
                              void* d_out, int out_size) {
    const float* ue = (const float*)d_in[0];
    const float* ie = (const float*)d_in[1];
    const float* av = (const float*)d_in[2];
    const int*   ar = (const int*)d_in[3];
    const int*   ac = (const int*)d_in[4];
    const int*   ul = (const int*)d_in[5];
    const int*   pl = (const int*)d_in[6];
    const int*   nl = (const int*)d_in[7];
    float* out = (float*)d_out;

    const int SCAN_BLOCKS = (N_NODESC + 1023) / 1024;
    const int SPMM_BLOCKS = (N_NODESC * 32 + 255) / 256;

    unsigned seeds[2] = {101u, 202u};
    unsigned fk[2][3][2];
    for (int vv = 0; vv < 2; vv++)
        for (int k = 0; k < 3; k++)
            tf2x32(0u, seeds[vv], 0u, (unsigned)k, fk[vv][k][0], fk[vv][k][1]);

    k_init<<<(N_NODESC * DIM + 255) / 256, 256>>>(ue, ie);
    k_hist<<<(NNZC + 255) / 256, 256>>>(ar);
    k_scan1<<<SCAN_BLOCKS, 1024>>>();
    k_scan2<<<1, 32>>>(SCAN_BLOCKS);
    k_scan3<<<SCAN_BLOCKS, 1024>>>();
    k_fill<<<(NNZC + 255) / 256, 256>>>(ar, ac, av);
    k_unique2<<<(2 * BATCHC + 255) / 256, 256>>>(ul, pl);

    // layer 1 (shared SpMM, warp-per-row) + fused layer-1 noise for both views
    k_spmm_e1_noise<<<SPMM_BLOCKS, 256>>>(fk[0][0][0], fk[0][0][1], fk[1][0][0], fk[1][0][1]);
    // fused layer 2: e2 and both-view y2 in ONE CSR pass (+ layer-2 noise)
    k_spmm_l2<<<SPMM_BLOCKS, 256>>>(fk[0][1][0], fk[0][1][1], fk[1][1][0], fk[1][1][1]);
    k_bpr<<<(BATCHC * 32) / 256, 256>>>(ul, pl, nl);
    k_vfinal<<<(2 * BATCHC * 32) / 256, 256>>>(fk[0][2][0], fk[0][2][1], fk[1][2][0], fk[1][2][1]);

    dim3 nce_grid(BATCHC / 128, NCE_CSPLIT, 2);
    k_nce<<<nce_grid, 128>>>();
    k_ncefin<<<(2 * BATCHC + 255) / 256, 256>>>();
    k_final<<<1, 32>>>(out);
}

// round 8
// speedup vs baseline: 1.0492x; 1.0492x over previous
#include <cuda_runtime.h>
#include <cstdint>

#define N_USERS 100000
#define N_ITEMS 50000
#define N_NODESC 150000
#define NNZC 2400000
#define DIM 64
#define BATCHC 4096
#define HALFC 4800000u
#define NPAIR 75000
#define EPSC 0.1f
#define INV_TEMP 5.0f

// ---------------- static device scratch (allocation-free) ----------------
__device__ float  g_e1 [N_NODESC * DIM];
__device__ float  g_e2 [N_NODESC * DIM];
__device__ float4 g_y1 [N_NODESC * 32];   // interleaved: (v1x,v1y,v2x,v2y) at [row*32+lane]
__device__ float4 g_y2 [N_NODESC * 32];
__device__ int2   g_cv[NNZC];
__device__ int    g_rowptr[N_NODESC + 1];
__device__ int    g_cursor[N_NODESC];
__device__ int    g_counts[N_NODESC];
__device__ int    g_blocksums[256];
__device__ int    g_flags[N_NODESC];
__device__ int    g_uidx[BATCHC];
__device__ int    g_iidx[BATCHC];
__device__ int    g_ucnt;
__device__ int    g_icnt;
__device__ float  g_V1u[BATCHC * DIM], g_V2u[BATCHC * DIM];
__device__ float  g_V1i[BATCHC * DIM], g_V2i[BATCHC * DIM];
__device__ float  g_posU[BATCHC], g_posI[BATCHC];
__device__ float  g_S[2 * BATCHC];
__device__ float  g_acc[8];               // 0 rec, 1 ssu, 2 ssp, 3 nceU, 4 nceI

// ---------------- threefry-2x32 (exact JAX schedule) ----------------
__host__ __device__ __forceinline__ unsigned rl32(unsigned x, int r) {
    return (x << r) | (x >> (32 - r));
}
__host__ __device__ __forceinline__ void tf2x32(unsigned k0, unsigned k1,
                                                unsigned x0, unsigned x1,
                                                unsigned& o0, unsigned& o1) {
    unsigned k2 = k0 ^ k1 ^ 0x1BD11BDAu;
    x0 += k0; x1 += k1;
#define TFR(r) { x0 += x1; x1 = rl32(x1, r); x1 ^= x0; }
    TFR(13) TFR(15) TFR(26) TFR(6)
    x0 += k1; x1 += k2 + 1u;
    TFR(17) TFR(29) TFR(16) TFR(24)
    x0 += k2; x1 += k0 + 2u;
    TFR(13) TFR(15) TFR(26) TFR(6)
    x0 += k0; x1 += k1 + 3u;
    TFR(17) TFR(29) TFR(16) TFR(24)
    x0 += k1; x1 += k2 + 4u;
    TFR(13) TFR(15) TFR(26) TFR(6)
    x0 += k2; x1 += k0 + 5u;
#undef TFR
    o0 = x0; o1 = x1;
}
__device__ __forceinline__ float u32_to_unit(unsigned b) {
    return __uint_as_float((b >> 9) | 0x3f800000u) - 1.0f;
}
__device__ __forceinline__ float wredsum(float v) {
#pragma unroll
    for (int o = 16; o; o >>= 1) v += __shfl_xor_sync(0xffffffffu, v, o);
    return v;
}
__device__ __forceinline__ float sgn(float x) {
    return (x > 0.f) ? 1.f : ((x < 0.f) ? -1.f : 0.f);
}

// per-row noise for standalone rows (used only in vfinal, ~8K rows)
__device__ __forceinline__ void row_noise(int row, int lane, unsigned k0, unsigned k1,
                                          float& nx, float& ny, float& sc) {
    int half = (row >= NPAIR);
    unsigned base = (unsigned)(half ? row - NPAIR : row) * 64u + (unsigned)(lane * 2);
    unsigned a0, a1, b0, b1;
    tf2x32(k0, k1, base, base + HALFC, a0, a1);
    tf2x32(k0, k1, base + 1u, base + 1u + HALFC, b0, b1);
    nx = u32_to_unit(half ? a1 : a0);
    ny = u32_to_unit(half ? b1 : b0);
    sc = EPSC * rsqrtf(wredsum(nx * nx + ny * ny));
}

// warp computes one CSR row (float2 source) at cols (2*lane, 2*lane+1); 4-wide MLP
__device__ __forceinline__ float2 csr_row(const float* __restrict__ x, int row, int lane) {
    int s = g_rowptr[row], e = g_rowptr[row + 1];
    float ax = 0.f, ay = 0.f, bx = 0.f, by = 0.f;
    float cx = 0.f, cy = 0.f, dx = 0.f, dy = 0.f;
    int i = s;
    for (; i + 3 < e; i += 4) {
        int2 c0 = g_cv[i], c1 = g_cv[i + 1], c2 = g_cv[i + 2], c3 = g_cv[i + 3];
        float2 p0 = ((const float2*)(x + (c0.x << 6)))[lane];
        float2 p1 = ((const float2*)(x + (c1.x << 6)))[lane];
        float2 p2 = ((const float2*)(x + (c2.x << 6)))[lane];
        float2 p3 = ((const float2*)(x + (c3.x << 6)))[lane];
        float v0 = __int_as_float(c0.y), v1 = __int_as_float(c1.y);
        float v2 = __int_as_float(c2.y), v3 = __int_as_float(c3.y);
        ax = fmaf(v0, p0.x, ax); ay = fmaf(v0, p0.y, ay);
        bx = fmaf(v1, p1.x, bx); by = fmaf(v1, p1.y, by);
        cx = fmaf(v2, p2.x, cx); cy = fmaf(v2, p2.y, cy);
        dx = fmaf(v3, p3.x, dx); dy = fmaf(v3, p3.y, dy);
    }
    for (; i < e; i++) {
        int2 c0 = g_cv[i];
        float2 p0 = ((const float2*)(x + (c0.x << 6)))[lane];
        float v0 = __int_as_float(c0.y);
        ax = fmaf(v0, p0.x, ax); ay = fmaf(v0, p0.y, ay);
    }
    return make_float2((ax + bx) + (cx + dx), (ay + by) + (cy + dy));
}

// layer-1 gather directly from the two input embedding arrays (no ego copy)
__device__ __forceinline__ float2 csr_row_in(const float* __restrict__ ue,
                                             const float* __restrict__ ie,
                                             int row, int lane) {
    int s = g_rowptr[row], e = g_rowptr[row + 1];
    float ax = 0.f, ay = 0.f, bx = 0.f, by = 0.f;
    float cx = 0.f, cy = 0.f, dx = 0.f, dy = 0.f;
    int i = s;
#define SRC(c) ((c) < N_USERS ? ue + ((c) << 6) : ie + (((c) - N_USERS) << 6))
    for (; i + 3 < e; i += 4) {
        int2 c0 = g_cv[i], c1 = g_cv[i + 1], c2 = g_cv[i + 2], c3 = g_cv[i + 3];
        float2 p0 = ((const float2*)SRC(c0.x))[lane];
        float2 p1 = ((const float2*)SRC(c1.x))[lane];
        float2 p2 = ((const float2*)SRC(c2.x))[lane];
        float2 p3 = ((const float2*)SRC(c3.x))[lane];
        float v0 = __int_as_float(c0.y), v1 = __int_as_float(c1.y);
        float v2 = __int_as_float(c2.y), v3 = __int_as_float(c3.y);
        ax = fmaf(v0, p0.x, ax); ay = fmaf(v0, p0.y, ay);
        bx = fmaf(v1, p1.x, bx); by = fmaf(v1, p1.y, by);
        cx = fmaf(v2, p2.x, cx); cy = fmaf(v2, p2.y, cy);
        dx = fmaf(v3, p3.x, dx); dy = fmaf(v3, p3.y, dy);
    }
    for (; i < e; i++) {
        int2 c0 = g_cv[i];
        float2 p0 = ((const float2*)SRC(c0.x))[lane];
        float v0 = __int_as_float(c0.y);
        ax = fmaf(v0, p0.x, ax); ay = fmaf(v0, p0.y, ay);
    }
#undef SRC
    return make_float2((ax + bx) + (cx + dx), (ay + by) + (cy + dy));
}

// warp computes one CSR row over interleaved float4 source; 4-wide MLP
__device__ __forceinline__ float4 csr_row4(const float4* __restrict__ x, int row, int lane) {
    int s = g_rowptr[row], e = g_rowptr[row + 1];
    float ax = 0.f, ay = 0.f, az = 0.f, aw = 0.f;
    float bx = 0.f, by = 0.f, bz = 0.f, bw = 0.f;
    int i = s;
    for (; i + 3 < e; i += 4) {
        int2 c0 = g_cv[i], c1 = g_cv[i + 1], c2 = g_cv[i + 2], c3 = g_cv[i + 3];
        float4 p0 = x[(c0.x << 5) + lane];
        float4 p1 = x[(c1.x << 5) + lane];
        float4 p2 = x[(c2.x << 5) + lane];
        float4 p3 = x[(c3.x << 5) + lane];
        float v0 = __int_as_float(c0.y), v1 = __int_as_float(c1.y);
        float v2 = __int_as_float(c2.y), v3 = __int_as_float(c3.y);
        ax = fmaf(v0, p0.x, ax); ay = fmaf(v0, p0.y, ay);
        az = fmaf(v0, p0.z, az); aw = fmaf(v0, p0.w, aw);
        bx = fmaf(v1, p1.x, bx); by = fmaf(v1, p1.y, by);
        bz = fmaf(v1, p1.z, bz); bw = fmaf(v1, p1.w, bw);
        ax = fmaf(v2, p2.x, ax); ay = fmaf(v2, p2.y, ay);
        az = fmaf(v2, p2.z, az); aw = fmaf(v2, p2.w, aw);
        bx = fmaf(v3, p3.x, bx); by = fmaf(v3, p3.y, by);
        bz = fmaf(v3, p3.z, bz); bw = fmaf(v3, p3.w, bw);
    }
    for (; i < e; i++) {
        int2 c0 = g_cv[i];
        float4 p0 = x[(c0.x << 5) + lane];
        float v0 = __int_as_float(c0.y);
        ax = fmaf(v0, p0.x, ax); ay = fmaf(v0, p0.y, ay);
        az = fmaf(v0, p0.z, az); aw = fmaf(v0, p0.w, aw);
    }
    return make_float4(ax + bx, ay + by, az + bz, aw + bw);
}

// fused: one CSR pass computing BOTH e2 (from g_e1, float2) and y2 (from g_y1, float4)
__device__ __forceinline__ void csr_row6(int row, int lane, float2& oe, float4& oy) {
    int s = g_rowptr[row], e = g_rowptr[row + 1];
    float ex0 = 0.f, ey0 = 0.f, ex1 = 0.f, ey1 = 0.f;
    float yx0 = 0.f, yy0 = 0.f, yz0 = 0.f, yw0 = 0.f;
    float yx1 = 0.f, yy1 = 0.f, yz1 = 0.f, yw1 = 0.f;
    int i = s;
    for (; i + 3 < e; i += 4) {
        int2 c0 = g_cv[i], c1 = g_cv[i + 1], c2 = g_cv[i + 2], c3 = g_cv[i + 3];
        float2 q0 = ((const float2*)(g_e1 + (c0.x << 6)))[lane];
        float2 q1 = ((const float2*)(g_e1 + (c1.x << 6)))[lane];
        float2 q2 = ((const float2*)(g_e1 + (c2.x << 6)))[lane];
        float2 q3 = ((const float2*)(g_e1 + (c3.x << 6)))[lane];
        float4 p0 = g_y1[(c0.x << 5) + lane];
        float4 p1 = g_y1[(c1.x << 5) + lane];
        float4 p2 = g_y1[(c2.x << 5) + lane];
        float4 p3 = g_y1[(c3.x << 5) + lane];
        float v0 = __int_as_float(c0.y), v1 = __int_as_float(c1.y);
        float v2 = __int_as_float(c2.y), v3 = __int_as_float(c3.y);
        ex0 = fmaf(v0, q0.x, ex0); ey0 = fmaf(v0, q0.y, ey0);
        ex1 = fmaf(v1, q1.x, ex1); ey1 = fmaf(v1, q1.y, ey1);
        ex0 = fmaf(v2, q2.x, ex0); ey0 = fmaf(v2, q2.y, ey0);
        ex1 = fmaf(v3, q3.x, ex1); ey1 = fmaf(v3, q3.y, ey1);
        yx0 = fmaf(v0, p0.x, yx0); yy0 = fmaf(v0, p0.y, yy0);
        yz0 = fmaf(v0, p0.z, yz0); yw0 = fmaf(v0, p0.w, yw0);
        yx1 = fmaf(v1, p1.x, yx1); yy1 = fmaf(v1, p1.y, yy1);
        yz1 = fmaf(v1, p1.z, yz1); yw1 = fmaf(v1, p1.w, yw1);
        yx0 = fmaf(v2, p2.x, yx0); yy0 = fmaf(v2, p2.y, yy0);
        yz0 = fmaf(v2, p2.z, yz0); yw0 = fmaf(v2, p2.w, yw0);
        yx1 = fmaf(v3, p3.x, yx1); yy1 = fmaf(v3, p3.y, yy1);
        yz1 = fmaf(v3, p3.z, yz1); yw1 = fmaf(v3, p3.w, yw1);
    }
    for (; i < e; i++) {
        int2 c0 = g_cv[i];
        float2 q0 = ((const float2*)(g_e1 + (c0.x << 6)))[lane];
        float4 p0 = g_y1[(c0.x << 5) + lane];
        float v0 = __int_as_float(c0.y);
        ex0 = fmaf(v0, q0.x, ex0); ey0 = fmaf(v0, q0.y, ey0);
        yx0 = fmaf(v0, p0.x, yx0); yy0 = fmaf(v0, p0.y, yy0);
        yz0 = fmaf(v0, p0.z, yz0); yw0 = fmaf(v0, p0.w, yw0);
    }
    oe = make_float2(ex0 + ex1, ey0 + ey1);
    oy = make_float4(yx0 + yx1, yy0 + yy1, yz0 + yz1, yw0 + yw1);
}

// ---------------- setup ----------------
__global__ void k_init() {
    int i = blockIdx.x * blockDim.x + threadIdx.x;
    if (i < N_NODESC) { g_flags[i] = 0; g_counts[i] = 0; }
    if (i < 2 * BATCHC) g_S[i] = 0.f;
    if (i < 8) g_acc[i] = 0.f;
    if (i == 0) { g_ucnt = 0; g_icnt = 0; }
}
__global__ void k_hist(const int* __restrict__ rows) {
    int i = blockIdx.x * blockDim.x + threadIdx.x;
    if (i < NNZC) atomicAdd(&g_counts[rows[i]], 1);
}
__global__ void k_scan1() {
    __shared__ int sh[1024];
    int g = blockIdx.x * 1024 + threadIdx.x;
    int v = (g < N_NODESC) ? g_counts[g] : 0;
    sh[threadIdx.x] = v;
    __syncthreads();
    for (int off = 1; off < 1024; off <<= 1) {
        int t = (threadIdx.x >= off) ? sh[threadIdx.x - off] : 0;
        __syncthreads();
        sh[threadIdx.x] += t;
        __syncthreads();
    }
    if (g < N_NODESC) g_rowptr[g] = sh[threadIdx.x] - v;
    if (threadIdx.x == 1023) g_blocksums[blockIdx.x] = sh[1023];
}
// parallel exclusive scan of 147 block sums (one block, 256 threads)
__global__ void k_scan2(int nblocks) {
    __shared__ int sh[256];
    int t = threadIdx.x;
    int v = (t < nblocks) ? g_blocksums[t] : 0;
    sh[t] = v;
    __syncthreads();
    for (int off = 1; off < 256; off <<= 1) {
        int p = (t >= off) ? sh[t - off] : 0;
        __syncthreads();
        sh[t] += p;
        __syncthreads();
    }
    if (t < nblocks) g_blocksums[t] = sh[t] - v;   // exclusive
    if (t == nblocks - 1) g_rowptr[N_NODESC] = sh[t];
}
__global__ void k_scan3() {
    int g = blockIdx.x * blockDim.x + threadIdx.x;
    if (g < N_NODESC) {
        int v = g_rowptr[g] + g_blocksums[g >> 10];
        g_rowptr[g] = v;
        g_cursor[g] = v;
    }
}
__global__ void k_fill(const int* __restrict__ rows, const int* __restrict__ cols,
                       const float* __restrict__ vals) {
    int i = blockIdx.x * blockDim.x + threadIdx.x;
    if (i < NNZC) {
        int p = atomicAdd(&g_cursor[rows[i]], 1);
        g_cv[p] = make_int2(cols[i], __float_as_int(vals[i]));
    }
}

// ---------------- e1 = A*[ue;ie] + fused layer-1 noise (block-paired tf sharing) ----------------
// Block = 8 warps: warps 0-3 rows pr..pr+3, warps 4-7 the +NPAIR partners.
// Low warps compute threefry for the pair and hand the partner outputs over smem.
__global__ void __launch_bounds__(256) k_spmm_e1_noise(const float* __restrict__ ue,
                                                       const float* __restrict__ ie,
                                                       unsigned f10, unsigned f11,
                                                       unsigned f20, unsigned f21) {
    int warp = threadIdx.x >> 5;
    int lane = threadIdx.x & 31;
    int sub = warp & 3;
    int hi = warp >> 2;
    int pr = blockIdx.x * 4 + sub;
    int row = pr + hi * NPAIR;
    __shared__ unsigned shn[2][4][32][2];
    float2 ea = csr_row_in(ue, ie, row, lane);
    unsigned myx[2], myy[2];
    if (!hi) {
        unsigned base = (unsigned)pr * 64u + (unsigned)(lane * 2);
#pragma unroll
        for (int vv = 0; vv < 2; vv++) {
            unsigned k0 = vv ? f20 : f10, k1 = vv ? f21 : f11;
            unsigned a0, a1, b0, b1;
            tf2x32(k0, k1, base, base + HALFC, a0, a1);
            tf2x32(k0, k1, base + 1u, base + 1u + HALFC, b0, b1);
            myx[vv] = a0; myy[vv] = b0;
            shn[vv][sub][lane][0] = a1;
            shn[vv][sub][lane][1] = b1;
        }
    }
    __syncthreads();
    if (hi) {
#pragma unroll
        for (int vv = 0; vv < 2; vv++) {
            myx[vv] = shn[vv][sub][lane][0];
            myy[vv] = shn[vv][sub][lane][1];
        }
    }
    ((float2*)(g_e1 + (row << 6)))[lane] = ea;
    float4 o;
    {
        float nx = u32_to_unit(myx[0]), ny = u32_to_unit(myy[0]);
        float sc = EPSC * rsqrtf(wredsum(nx * nx + ny * ny));
        o.x = ea.x + sgn(ea.x) * nx * sc;
        o.y = ea.y + sgn(ea.y) * ny * sc;
    }
    {
        float nx = u32_to_unit(myx[1]), ny = u32_to_unit(myy[1]);
        float sc = EPSC * rsqrtf(wredsum(nx * nx + ny * ny));
        o.z = ea.x + sgn(ea.x) * nx * sc;
        o.w = ea.y + sgn(ea.y) * ny * sc;
    }
    g_y1[(row << 5) + lane] = o;
}

// ---------------- fused layer-2: e2 AND y2 in one CSR pass (paired tf sharing) ----------------
__global__ void __launch_bounds__(256) k_spmm_l2(unsigned f10, unsigned f11,
                                                 unsigned f20, unsigned f21) {
    int warp = threadIdx.x >> 5;
    int lane = threadIdx.x & 31;
    int sub = warp & 3;
    int hi = warp >> 2;
    int pr = blockIdx.x * 4 + sub;
    int row = pr + hi * NPAIR;
    __shared__ unsigned shn[2][4][32][2];
    float2 oe;
    float4 oy;
    csr_row6(row, lane, oe, oy);
    unsigned myx[2], myy[2];
    if (!hi) {
        unsigned base = (unsigned)pr * 64u + (unsigned)(lane * 2);
#pragma unroll
        for (int vv = 0; vv < 2; vv++) {
            unsigned k0 = vv ? f20 : f10, k1 = vv ? f21 : f11;
            unsigned a0, a1, b0, b1;
            tf2x32(k0, k1, base, base + HALFC, a0, a1);
            tf2x32(k0, k1, base + 1u, base + 1u + HALFC, b0, b1);
            myx[vv] = a0; myy[vv] = b0;
            shn[vv][sub][lane][0] = a1;
            shn[vv][sub][lane][1] = b1;
        }
    }
    __syncthreads();
    if (hi) {
#pragma unroll
        for (int vv = 0; vv < 2; vv++) {
            myx[vv] = shn[vv][sub][lane][0];
            myy[vv] = shn[vv][sub][lane][1];
        }
    }
    ((float2*)(g_e2 + (row << 6)))[lane] = oe;
    {
        float nx = u32_to_unit(myx[0]), ny = u32_to_unit(myy[0]);
        float sc = EPSC * rsqrtf(wredsum(nx * nx + ny * ny));
        oy.x += sgn(oy.x) * nx * sc;
        oy.y += sgn(oy.y) * ny * sc;
    }
    {
        float nx = u32_to_unit(myx[1]), ny = u32_to_unit(myy[1]);
        float sc = EPSC * rsqrtf(wredsum(nx * nx + ny * ny));
        oy.z += sgn(oy.z) * nx * sc;
        oy.w += sgn(oy.w) * ny * sc;
    }
    g_y2[(row << 5) + lane] = oy;
}

// ---------------- BPR: warp per batch entry, layer-3 rows on the fly ----------------
__global__ void __launch_bounds__(256) k_bpr(const int* __restrict__ ul,
                                             const int* __restrict__ pl,
                                             const int* __restrict__ nl) {
    int w = (blockIdx.x * blockDim.x + threadIdx.x) >> 5;
    int lane = threadIdx.x & 31;
    if (w >= BATCHC) return;
    const float third = 1.f / 3.f;
    int ru = ul[w];
    int rp = N_USERS + pl[w];
    int rn = N_USERS + nl[w];
    float2 u3 = csr_row(g_e2, ru, lane);
    float2 p3 = csr_row(g_e2, rp, lane);
    float2 n3 = csr_row(g_e2, rn, lane);
    float2 u1 = ((const float2*)(g_e1 + (ru << 6)))[lane];
    float2 u2 = ((const float2*)(g_e2 + (ru << 6)))[lane];
    float2 p1 = ((const float2*)(g_e1 + (rp << 6)))[lane];
    float2 p2 = ((const float2*)(g_e2 + (rp << 6)))[lane];
    float2 n1 = ((const float2*)(g_e1 + (rn << 6)))[lane];
    float2 n2 = ((const float2*)(g_e2 + (rn << 6)))[lane];
    float ux = (u1.x + u2.x + u3.x) * third, uy = (u1.y + u2.y + u3.y) * third;
    float px = (p1.x + p2.x + p3.x) * third, py = (p1.y + p2.y + p3.y) * third;
    float nx = (n1.x + n2.x + n3.x) * third, ny = (n1.y + n2.y + n3.y) * third;
    float pos = wredsum(ux * px + uy * py);
    float neg = wredsum(ux * nx + uy * ny);
    float ssu = wredsum(ux * ux + uy * uy);
    float ssp = wredsum(px * px + py * py);
    if (lane == 0) {
        float d = pos - neg;
        float sig = 1.f / (1.f + expf(-d));
        atomicAdd(&g_acc[0], -logf(1e-7f + sig));
        atomicAdd(&g_acc[1], ssu);
        atomicAdd(&g_acc[2], ssp);
    }
}

// ---------------- order-free unique (both lists in one launch) ----------------
__global__ void k_unique2(const int* __restrict__ ul, const int* __restrict__ pl) {
    int i = blockIdx.x * blockDim.x + threadIdx.x;
    if (i >= 2 * BATCHC) return;
    int which = (i >= BATCHC);
    int j = which ? i - BATCHC : i;
    int v = which ? pl[j] : ul[j];
    int fidx = which ? (N_USERS + v) : v;
    if (atomicExch(&g_flags[fidx], 1) == 0) {
        int p = atomicAdd(which ? &g_icnt : &g_ucnt, 1);
        (which ? g_iidx : g_uidx)[p] = v;
    }
}

// ---------------- finalize both views: layer-3 + noise + normalize + pos ----------------
__global__ void __launch_bounds__(256) k_vfinal(unsigned f10, unsigned f11,
                                                unsigned f20, unsigned f21) {
    int w = (blockIdx.x * blockDim.x + threadIdx.x) >> 5;
    int lane = threadIdx.x & 31;
    if (w >= 2 * BATCHC) return;
    int isItem = (w >= BATCHC);
    int j = isItem ? w - BATCHC : w;
    int cnt = isItem ? g_icnt : g_ucnt;
    if (j >= cnt) return;
    int row = isItem ? (N_USERS + g_iidx[j]) : g_uidx[j];
    float4 a3 = csr_row4(g_y2, row, lane);
    float nx, ny, sc;
    row_noise(row, lane, f10, f11, nx, ny, sc);
    a3.x += sgn(a3.x) * nx * sc;
    a3.y += sgn(a3.y) * ny * sc;
    row_noise(row, lane, f20, f21, nx, ny, sc);
    a3.z += sgn(a3.z) * nx * sc;
    a3.w += sgn(a3.w) * ny * sc;
    float4 y1r = g_y1[(row << 5) + lane];
    float4 y2r = g_y2[(row << 5) + lane];
    float s1x = y1r.x + y2r.x + a3.x;
    float s1y = y1r.y + y2r.y + a3.y;
    float inv1 = rsqrtf(wredsum(s1x * s1x + s1y * s1y));
    s1x *= inv1; s1y *= inv1;
    float s2x = y1r.z + y2r.z + a3.z;
    float s2y = y1r.w + y2r.w + a3.w;
    float inv2 = rsqrtf(wredsum(s2x * s2x + s2y * s2y));
    s2x *= inv2; s2y *= inv2;
    float* d1 = isItem ? g_V1i : g_V1u;
    float* d2 = isItem ? g_V2i : g_V2u;
    ((float2*)(d1 + (j << 6)))[lane] = make_float2(s1x, s1y);
    ((float2*)(d2 + (j << 6)))[lane] = make_float2(s2x, s2y);
    float d = wredsum(s2x * s1x + s2y * s1y);
    if (lane == 0) (isItem ? g_posI : g_posU)[j] = d * INV_TEMP;
}

// ---------------- InfoNCE (both halves via grid.z) ----------------
#define NCE_CSPLIT 16
#define NCE_COLS (BATCHC / NCE_CSPLIT)
__global__ void __launch_bounds__(128) k_nce() {
    int which = blockIdx.z;
    const float* __restrict__ V1 = which ? g_V1i : g_V1u;
    const float* __restrict__ V2 = which ? g_V2i : g_V2u;
    float* __restrict__ S = g_S + which * BATCHC;
    int U = which ? g_icnt : g_ucnt;
    int r = blockIdx.x * 128 + threadIdx.x;
    float4 v[16];
    if (r < U) {
        const float4* p = (const float4*)(V1 + (r << 6));
#pragma unroll
        for (int i = 0; i < 16; i++) v[i] = p[i];
    }
    __shared__ float sh[128 * DIM];
    float s = 0.f;
    int cbegin = blockIdx.y * NCE_COLS;
    for (int t = cbegin; t < cbegin + NCE_COLS; t += 128) {
        int cmax = U - t; if (cmax > 128) cmax = 128;
        if (cmax > 0) {
            const float4* src = (const float4*)(V2 + (t << 6));
            float4* d4 = (float4*)sh;
            for (int idx = threadIdx.x; idx < cmax * 16; idx += 128) d4[idx] = src[idx];
        }
        __syncthreads();
        if (r < U && cmax > 0) {
            for (int cc = 0; cc < cmax; cc++) {
                const float4* q = (const float4*)(sh + cc * DIM);
                float d0 = 0.f, d1 = 0.f, d2 = 0.f, d3 = 0.f;
#pragma unroll
                for (int i = 0; i < 16; i += 4) {
                    float4 q0 = q[i], q1 = q[i+1], q2 = q[i+2], q3 = q[i+3];
                    d0 = fmaf(v[i].x, q0.x, fmaf(v[i].y, q0.y, fmaf(v[i].z, q0.z, fmaf(v[i].w, q0.w, d0))));
                    d1 = fmaf(v[i+1].x, q1.x, fmaf(v[i+1].y, q1.y, fmaf(v[i+1].z, q1.z, fmaf(v[i+1].w, q1.w, d1))));
                    d2 = fmaf(v[i+2].x, q2.x, fmaf(v[i+2].y, q2.y, fmaf(v[i+2].z, q2.z, fmaf(v[i+2].w, q2.w, d2))));
                    d3 = fmaf(v[i+3].x, q3.x, fmaf(v[i+3].y, q3.y, fmaf(v[i+3].z, q3.z, fmaf(v[i+3].w, q3.w, d3))));
                }
                float dot = (d0 + d1) + (d2 + d3);
                s += __expf(dot * INV_TEMP - 5.0f);
            }
        }
        __syncthreads();
    }
    if (r < U && s != 0.f) atomicAdd(&S[r], s);
}

__global__ void __launch_bounds__(256) k_ncefin() {
    int i = blockIdx.x * blockDim.x + threadIdx.x;
    int which = (i >= BATCHC);
    int j = i - which * BATCHC;
    int U = which ? g_icnt : g_ucnt;
    float c = 0.f;
    if (i < 2 * BATCHC && j < U)
        c = 5.0f + logf(g_S[i]) - (which ? g_posI[j] : g_posU[j]);
    c = wredsum(c);
    if ((threadIdx.x & 31) == 0 && c != 0.f)
        atomicAdd(&g_acc[3 + which], c);
}

__global__ void k_final(float* out) {
    if (threadIdx.x == 0) {
        float rec = g_acc[0] / (float)BATCHC;
        float reg = 1e-4f * (sqrtf(g_acc[1]) + sqrtf(g_acc[2]));
        float cl = 0.2f * (g_acc[3] / (float)g_ucnt + g_acc[4] / (float)g_icnt);
        out[0] = rec + reg + cl;
        out[1] = cl;
    }
}

// ---------------- launch ----------------
extern "C" void kernel_launch(void* const* d_in, const int* in_sizes, int n_in,
                              void* d_out, int out_size) {
    const float* ue = (const float*)d_in[0];
    const float* ie = (const float*)d_in[1];
    const float* av = (const float*)d_in[2];
    const int*   ar = (const int*)d_in[3];
    const int*   ac = (const int*)d_in[4];
    const int*   ul = (const int*)d_in[5];
    const int*   pl = (const int*)d_in[6];
    const int*   nl = (const int*)d_in[7];
    float* out = (float*)d_out;

    const int SCAN_BLOCKS = (N_NODESC + 1023) / 1024;
    const int PAIRED_BLOCKS = NPAIR / 4;   // 18750: 4 row-pairs per 8-warp block

    unsigned seeds[2] = {101u, 202u};
    unsigned fk[2][3][2];
    for (int vv = 0; vv < 2; vv++)
        for (int k = 0; k < 3; k++)
            tf2x32(0u, seeds[vv], 0u, (unsigned)k, fk[vv][k][0], fk[vv][k][1]);

    k_init<<<(N_NODESC + 255) / 256, 256>>>();
    k_hist<<<(NNZC + 255) / 256, 256>>>(ar);
    k_scan1<<<SCAN_BLOCKS, 1024>>>();
    k_scan2<<<1, 256>>>(SCAN_BLOCKS);
    k_scan3<<<SCAN_BLOCKS, 1024>>>();
    k_fill<<<(NNZC + 255) / 256, 256>>>(ar, ac, av);
    k_unique2<<<(2 * BATCHC + 255) / 256, 256>>>(ul, pl);

    // layer 1: gather straight from inputs + paired-tf fused noise (both views)
    k_spmm_e1_noise<<<PAIRED_BLOCKS, 256>>>(ue, ie,
        fk[0][0][0], fk[0][0][1], fk[1][0][0], fk[1][0][1]);
    // layer 2: e2 and both-view y2 in one CSR pass + paired-tf fused noise
    k_spmm_l2<<<PAIRED_BLOCKS, 256>>>(fk[0][1][0], fk[0][1][1], fk[1][1][0], fk[1][1][1]);
    k_bpr<<<(BATCHC * 32) / 256, 256>>>(ul, pl, nl);
    k_vfinal<<<(2 * BATCHC * 32) / 256, 256>>>(fk[0][2][0], fk[0][2][1], fk[1][2][0], fk[1][2][1]);

    dim3 nce_grid(BATCHC / 128, NCE_CSPLIT, 2);
    k_nce<<<nce_grid, 128>>>();
    k_ncefin<<<(2 * BATCHC + 255) / 256, 256>>>();
    k_final<<<1, 32>>>(out);
}

// round 10
// speedup vs baseline: 1.1874x; 1.1317x over previous
#include <cuda_runtime.h>
#include <cuda_fp16.h>
#include <cstdint>

#define N_USERS 100000
#define N_ITEMS 50000
#define N_NODESC 150000
#define NNZC 2400000
#define DIM 64
#define BATCHC 4096
#define HALFC 4800000u
#define NPAIR 75000
#define EPSC 0.1f
#define INV_TEMP 5.0f

// ---------------- static device scratch (allocation-free) ----------------
__device__ float  g_e1 [N_NODESC * DIM];
__device__ float  g_e2 [N_NODESC * DIM];
__device__ uint2  g_d1 [N_NODESC * 32];   // half4 noise offsets (v1x,v1y,v2x,v2y) at [row*32+lane]
__device__ uint2  g_d2 [N_NODESC * 32];   // layer-2 view delta = A*d1 + noise2 offsets
__device__ int2   g_cv[NNZC];
__device__ int    g_rowptr[N_NODESC + 1];
__device__ int    g_cursor[N_NODESC];
__device__ int    g_counts[N_NODESC];
__device__ int    g_blocksums[256];
__device__ int    g_flags[N_NODESC];
__device__ int    g_uidx[BATCHC];
__device__ int    g_iidx[BATCHC];
__device__ int    g_ucnt;
__device__ int    g_icnt;
__device__ float  g_V1u[BATCHC * DIM], g_V2u[BATCHC * DIM];
__device__ float  g_V1i[BATCHC * DIM], g_V2i[BATCHC * DIM];
__device__ float  g_posU[BATCHC], g_posI[BATCHC];
__device__ float  g_S[2 * BATCHC];
__device__ float  g_acc[8];               // 0 rec, 1 ssu, 2 ssp, 3 nceU, 4 nceI

// ---------------- half4 pack/unpack ----------------
__device__ __forceinline__ uint2 pack4h(float a, float b, float c, float d) {
    __half2 lo = __floats2half2_rn(a, b);
    __half2 hi = __floats2half2_rn(c, d);
    uint2 r;
    r.x = *(const unsigned*)&lo;
    r.y = *(const unsigned*)&hi;
    return r;
}
__device__ __forceinline__ float4 unpack4h(uint2 u) {
    float2 lo = __half22float2(*(const __half2*)&u.x);
    float2 hi = __half22float2(*(const __half2*)&u.y);
    return make_float4(lo.x, lo.y, hi.x, hi.y);
}

// ---------------- threefry-2x32 (exact JAX schedule) ----------------
__host__ __device__ __forceinline__ unsigned rl32(unsigned x, int r) {
    return (x << r) | (x >> (32 - r));
}
__host__ __device__ __forceinline__ void tf2x32(unsigned k0, unsigned k1,
                                                unsigned x0, unsigned x1,
                                                unsigned& o0, unsigned& o1) {
    unsigned k2 = k0 ^ k1 ^ 0x1BD11BDAu;
    x0 += k0; x1 += k1;
#define TFR(r) { x0 += x1; x1 = rl32(x1, r); x1 ^= x0; }
    TFR(13) TFR(15) TFR(26) TFR(6)
    x0 += k1; x1 += k2 + 1u;
    TFR(17) TFR(29) TFR(16) TFR(24)
    x0 += k2; x1 += k0 + 2u;
    TFR(13) TFR(15) TFR(26) TFR(6)
    x0 += k0; x1 += k1 + 3u;
    TFR(17) TFR(29) TFR(16) TFR(24)
    x0 += k1; x1 += k2 + 4u;
    TFR(13) TFR(15) TFR(26) TFR(6)
    x0 += k2; x1 += k0 + 5u;
#undef TFR
    o0 = x0; o1 = x1;
}
__device__ __forceinline__ float u32_to_unit(unsigned b) {
    return __uint_as_float((b >> 9) | 0x3f800000u) - 1.0f;
}
__device__ __forceinline__ float wredsum(float v) {
#pragma unroll
    for (int o = 16; o; o >>= 1) v += __shfl_xor_sync(0xffffffffu, v, o);
    return v;
}
__device__ __forceinline__ float sgn(float x) {
    return (x > 0.f) ? 1.f : ((x < 0.f) ? -1.f : 0.f);
}

// per-row noise for standalone rows (vfinal only, ~8K rows)
__device__ __forceinline__ void row_noise(int row, int lane, unsigned k0, unsigned k1,
                                          float& nx, float& ny, float& sc) {
    int half = (row >= NPAIR);
    unsigned base = (unsigned)(half ? row - NPAIR : row) * 64u + (unsigned)(lane * 2);
    unsigned a0, a1, b0, b1;
    tf2x32(k0, k1, base, base + HALFC, a0, a1);
    tf2x32(k0, k1, base + 1u, base + 1u + HALFC, b0, b1);
    nx = u32_to_unit(half ? a1 : a0);
    ny = u32_to_unit(half ? b1 : b0);
    sc = EPSC * rsqrtf(wredsum(nx * nx + ny * ny));
}

// warp computes one CSR row (float2 source); 4-wide MLP
__device__ __forceinline__ float2 csr_row(const float* __restrict__ x, int row, int lane) {
    int s = g_rowptr[row], e = g_rowptr[row + 1];
    float ax = 0.f, ay = 0.f, bx = 0.f, by = 0.f;
    float cx = 0.f, cy = 0.f, dx = 0.f, dy = 0.f;
    int i = s;
    for (; i + 3 < e; i += 4) {
        int2 c0 = g_cv[i], c1 = g_cv[i + 1], c2 = g_cv[i + 2], c3 = g_cv[i + 3];
        float2 p0 = ((const float2*)(x + (c0.x << 6)))[lane];
        float2 p1 = ((const float2*)(x + (c1.x << 6)))[lane];
        float2 p2 = ((const float2*)(x + (c2.x << 6)))[lane];
        float2 p3 = ((const float2*)(x + (c3.x << 6)))[lane];
        float v0 = __int_as_float(c0.y), v1 = __int_as_float(c1.y);
        float v2 = __int_as_float(c2.y), v3 = __int_as_float(c3.y);
        ax = fmaf(v0, p0.x, ax); ay = fmaf(v0, p0.y, ay);
        bx = fmaf(v1, p1.x, bx); by = fmaf(v1, p1.y, by);
        cx = fmaf(v2, p2.x, cx); cy = fmaf(v2, p2.y, cy);
        dx = fmaf(v3, p3.x, dx); dy = fmaf(v3, p3.y, dy);
    }
    for (; i < e; i++) {
        int2 c0 = g_cv[i];
        float2 p0 = ((const float2*)(x + (c0.x << 6)))[lane];
        float v0 = __int_as_float(c0.y);
        ax = fmaf(v0, p0.x, ax); ay = fmaf(v0, p0.y, ay);
    }
    return make_float2((ax + bx) + (cx + dx), (ay + by) + (cy + dy));
}

// layer-1 gather directly from the two input embedding arrays
__device__ __forceinline__ float2 csr_row_in(const float* __restrict__ ue,
                                             const float* __restrict__ ie,
                                             int row, int lane) {
    int s = g_rowptr[row], e = g_rowptr[row + 1];
    float ax = 0.f, ay = 0.f, bx = 0.f, by = 0.f;
    float cx = 0.f, cy = 0.f, dx = 0.f, dy = 0.f;
    int i = s;
#define SRC(c) ((c) < N_USERS ? ue + ((c) << 6) : ie + (((c) - N_USERS) << 6))
    for (; i + 3 < e; i += 4) {
        int2 c0 = g_cv[i], c1 = g_cv[i + 1], c2 = g_cv[i + 2], c3 = g_cv[i + 3];
        float2 p0 = ((const float2*)SRC(c0.x))[lane];
        float2 p1 = ((const float2*)SRC(c1.x))[lane];
        float2 p2 = ((const float2*)SRC(c2.x))[lane];
        float2 p3 = ((const float2*)SRC(c3.x))[lane];
        float v0 = __int_as_float(c0.y), v1 = __int_as_float(c1.y);
        float v2 = __int_as_float(c2.y), v3 = __int_as_float(c3.y);
        ax = fmaf(v0, p0.x, ax); ay = fmaf(v0, p0.y, ay);
        bx = fmaf(v1, p1.x, bx); by = fmaf(v1, p1.y, by);
        cx = fmaf(v2, p2.x, cx); cy = fmaf(v2, p2.y, cy);
        dx = fmaf(v3, p3.x, dx); dy = fmaf(v3, p3.y, dy);
    }
    for (; i < e; i++) {
        int2 c0 = g_cv[i];
        float2 p0 = ((const float2*)SRC(c0.x))[lane];
        float v0 = __int_as_float(c0.y);
        ax = fmaf(v0, p0.x, ax); ay = fmaf(v0, p0.y, ay);
    }
#undef SRC
    return make_float2((ax + bx) + (cx + dx), (ay + by) + (cy + dy));
}

// one CSR pass over e1 (float2) + d1 (half4): se = A*e1, sd = A*d1
__device__ __forceinline__ void csr_row_l2(int row, int lane, float2& se, float4& sd) {
    int s = g_rowptr[row], e = g_rowptr[row + 1];
    float ex0 = 0.f, ey0 = 0.f, ex1 = 0.f, ey1 = 0.f;
    float dx0 = 0.f, dy0 = 0.f, dz0 = 0.f, dw0 = 0.f;
    float dx1 = 0.f, dy1 = 0.f, dz1 = 0.f, dw1 = 0.f;
    int i = s;
    for (; i + 3 < e; i += 4) {
        int2 c0 = g_cv[i], c1 = g_cv[i + 1], c2 = g_cv[i + 2], c3 = g_cv[i + 3];
        float2 q0 = ((const float2*)(g_e1 + (c0.x << 6)))[lane];
        float2 q1 = ((const float2*)(g_e1 + (c1.x << 6)))[lane];
        float2 q2 = ((const float2*)(g_e1 + (c2.x << 6)))[lane];
        float2 q3 = ((const float2*)(g_e1 + (c3.x << 6)))[lane];
        uint2 u0 = g_d1[(c0.x << 5) + lane];
        uint2 u1 = g_d1[(c1.x << 5) + lane];
        uint2 u2 = g_d1[(c2.x << 5) + lane];
        uint2 u3 = g_d1[(c3.x << 5) + lane];
        float v0 = __int_as_float(c0.y), v1 = __int_as_float(c1.y);
        float v2 = __int_as_float(c2.y), v3 = __int_as_float(c3.y);
        float4 p0 = unpack4h(u0), p1 = unpack4h(u1), p2 = unpack4h(u2), p3 = unpack4h(u3);
        ex0 = fmaf(v0, q0.x, ex0); ey0 = fmaf(v0, q0.y, ey0);
        ex1 = fmaf(v1, q1.x, ex1); ey1 = fmaf(v1, q1.y, ey1);
        ex0 = fmaf(v2, q2.x, ex0); ey0 = fmaf(v2, q2.y, ey0);
        ex1 = fmaf(v3, q3.x, ex1); ey1 = fmaf(v3, q3.y, ey1);
        dx0 = fmaf(v0, p0.x, dx0); dy0 = fmaf(v0, p0.y, dy0);
        dz0 = fmaf(v0, p0.z, dz0); dw0 = fmaf(v0, p0.w, dw0);
        dx1 = fmaf(v1, p1.x, dx1); dy1 = fmaf(v1, p1.y, dy1);
        dz1 = fmaf(v1, p1.z, dz1); dw1 = fmaf(v1, p1.w, dw1);
        dx0 = fmaf(v2, p2.x, dx0); dy0 = fmaf(v2, p2.y, dy0);
        dz0 = fmaf(v2, p2.z, dz0); dw0 = fmaf(v2, p2.w, dw0);
        dx1 = fmaf(v3, p3.x, dx1); dy1 = fmaf(v3, p3.y, dy1);
        dz1 = fmaf(v3, p3.z, dz1); dw1 = fmaf(v3, p3.w, dw1);
    }
    for (; i < e; i++) {
        int2 c0 = g_cv[i];
        float2 q0 = ((const float2*)(g_e1 + (c0.x << 6)))[lane];
        float4 p0 = unpack4h(g_d1[(c0.x << 5) + lane]);
        float v0 = __int_as_float(c0.y);
        ex0 = fmaf(v0, q0.x, ex0); ey0 = fmaf(v0, q0.y, ey0);
        dx0 = fmaf(v0, p0.x, dx0); dy0 = fmaf(v0, p0.y, dy0);
        dz0 = fmaf(v0, p0.z, dz0); dw0 = fmaf(v0, p0.w, dw0);
    }
    se = make_float2(ex0 + ex1, ey0 + ey1);
    sd = make_float4(dx0 + dx1, dy0 + dy1, dz0 + dz1, dw0 + dw1);
}

// layer-3 view gather: A*(e2 + d2) for one row, both views
__device__ __forceinline__ float4 csr_row_l3(int row, int lane) {
    int s = g_rowptr[row], e = g_rowptr[row + 1];
    float ax = 0.f, ay = 0.f, az = 0.f, aw = 0.f;
    float bx = 0.f, by = 0.f, bz = 0.f, bw = 0.f;
    int i = s;
    for (; i + 1 < e; i += 2) {
        int2 c0 = g_cv[i], c1 = g_cv[i + 1];
        float2 q0 = ((const float2*)(g_e2 + (c0.x << 6)))[lane];
        float2 q1 = ((const float2*)(g_e2 + (c1.x << 6)))[lane];
        float4 p0 = unpack4h(g_d2[(c0.x << 5) + lane]);
        float4 p1 = unpack4h(g_d2[(c1.x << 5) + lane]);
        float v0 = __int_as_float(c0.y), v1 = __int_as_float(c1.y);
        ax = fmaf(v0, q0.x + p0.x, ax); ay = fmaf(v0, q0.y + p0.y, ay);
        az = fmaf(v0, q0.x + p0.z, az); aw = fmaf(v0, q0.y + p0.w, aw);
        bx = fmaf(v1, q1.x + p1.x, bx); by = fmaf(v1, q1.y + p1.y, by);
        bz = fmaf(v1, q1.x + p1.z, bz); bw = fmaf(v1, q1.y + p1.w, bw);
    }
    if (i < e) {
        int2 c0 = g_cv[i];
        float2 q0 = ((const float2*)(g_e2 + (c0.x << 6)))[lane];
        float4 p0 = unpack4h(g_d2[(c0.x << 5) + lane]);
        float v0 = __int_as_float(c0.y);
        ax = fmaf(v0, q0.x + p0.x, ax); ay = fmaf(v0, q0.y + p0.y, ay);
        az = fmaf(v0, q0.x + p0.z, az); aw = fmaf(v0, q0.y + p0.w, aw);
    }
    return make_float4(ax + bx, ay + by, az + bz, aw + bw);
}

// ---------------- setup ----------------
__global__ void k_init() {
    int i = blockIdx.x * blockDim.x + threadIdx.x;
    if (i < N_NODESC) { g_flags[i] = 0; g_counts[i] = 0; }
    if (i < 2 * BATCHC) g_S[i] = 0.f;
    if (i < 8) g_acc[i] = 0.f;
    if (i == 0) { g_ucnt = 0; g_icnt = 0; }
}
__global__ void k_hist(const int* __restrict__ rows) {
    int i = blockIdx.x * blockDim.x + threadIdx.x;
    if (i < NNZC) atomicAdd(&g_counts[rows[i]], 1);
}
__global__ void k_scan1() {
    __shared__ int sh[1024];
    int g = blockIdx.x * 1024 + threadIdx.x;
    int v = (g < N_NODESC) ? g_counts[g] : 0;
    sh[threadIdx.x] = v;
    __syncthreads();
    for (int off = 1; off < 1024; off <<= 1) {
        int t = (threadIdx.x >= off) ? sh[threadIdx.x - off] : 0;
        __syncthreads();
        sh[threadIdx.x] += t;
        __syncthreads();
    }
    if (g < N_NODESC) g_rowptr[g] = sh[threadIdx.x] - v;
    if (threadIdx.x == 1023) g_blocksums[blockIdx.x] = sh[1023];
}
__global__ void k_scan2(int nblocks) {
    __shared__ int sh[256];
    int t = threadIdx.x;
    int v = (t < nblocks) ? g_blocksums[t] : 0;
    sh[t] = v;
    __syncthreads();
    for (int off = 1; off < 256; off <<= 1) {
        int p = (t >= off) ? sh[t - off] : 0;
        __syncthreads();
        sh[t] += p;
        __syncthreads();
    }
    if (t < nblocks) g_blocksums[t] = sh[t] - v;   // exclusive
    if (t == nblocks - 1) g_rowptr[N_NODESC] = sh[t];
}
__global__ void k_scan3() {
    int g = blockIdx.x * blockDim.x + threadIdx.x;
    if (g < N_NODESC) {
        int v = g_rowptr[g] + g_blocksums[g >> 10];
        g_rowptr[g] = v;
        g_cursor[g] = v;
    }
}
__global__ void k_fill(const int* __restrict__ rows, const int* __restrict__ cols,
                       const float* __restrict__ vals) {
    int i = blockIdx.x * blockDim.x + threadIdx.x;
    if (i < NNZC) {
        int p = atomicAdd(&g_cursor[rows[i]], 1);
        g_cv[p] = make_int2(cols[i], __float_as_int(vals[i]));
    }
}

// ---------------- layer 1: e1 = A*[ue;ie]; d1 = fp16 noise offsets (paired tf) ----------------
__global__ void __launch_bounds__(256) k_spmm_e1_noise(const float* __restrict__ ue,
                                                       const float* __restrict__ ie,
                                                       unsigned f10, unsigned f11,
                                                       unsigned f20, unsigned f21) {
    int warp = threadIdx.x >> 5;
    int lane = threadIdx.x & 31;
    int sub = warp & 3;
    int hi = warp >> 2;
    int pr = blockIdx.x * 4 + sub;
    int row = pr + hi * NPAIR;
    __shared__ unsigned shn[2][4][32][2];
    float2 ea = csr_row_in(ue, ie, row, lane);
    unsigned myx[2], myy[2];
    if (!hi) {
        unsigned base = (unsigned)pr * 64u + (unsigned)(lane * 2);
#pragma unroll
        for (int vv = 0; vv < 2; vv++) {
            unsigned k0 = vv ? f20 : f10, k1 = vv ? f21 : f11;
            unsigned a0, a1, b0, b1;
            tf2x32(k0, k1, base, base + HALFC, a0, a1);
            tf2x32(k0, k1, base + 1u, base + 1u + HALFC, b0, b1);
            myx[vv] = a0; myy[vv] = b0;
            shn[vv][sub][lane][0] = a1;
            shn[vv][sub][lane][1] = b1;
        }
    }
    __syncthreads();
    if (hi) {
#pragma unroll
        for (int vv = 0; vv < 2; vv++) {
            myx[vv] = shn[vv][sub][lane][0];
            myy[vv] = shn[vv][sub][lane][1];
        }
    }
    ((float2*)(g_e1 + (row << 6)))[lane] = ea;
    float o1x, o1y, o2x, o2y;
    {
        float nx = u32_to_unit(myx[0]), ny = u32_to_unit(myy[0]);
        float sc = EPSC * rsqrtf(wredsum(nx * nx + ny * ny));
        o1x = sgn(ea.x) * nx * sc;
        o1y = sgn(ea.y) * ny * sc;
    }
    {
        float nx = u32_to_unit(myx[1]), ny = u32_to_unit(myy[1]);
        float sc = EPSC * rsqrtf(wredsum(nx * nx + ny * ny));
        o2x = sgn(ea.x) * nx * sc;
        o2y = sgn(ea.y) * ny * sc;
    }
    g_d1[(row << 5) + lane] = pack4h(o1x, o1y, o2x, o2y);
}

// ---------------- layer 2: e2 = A*e1; d2 = A*d1 + noise2 offsets (paired tf) ----------------
__global__ void __launch_bounds__(256) k_spmm_l2(unsigned f10, unsigned f11,
                                                 unsigned f20, unsigned f21) {
    int warp = threadIdx.x >> 5;
    int lane = threadIdx.x & 31;
    int sub = warp & 3;
    int hi = warp >> 2;
    int pr = blockIdx.x * 4 + sub;
    int row = pr + hi * NPAIR;
    __shared__ unsigned shn[2][4][32][2];
    float2 se;
    float4 sd;
    csr_row_l2(row, lane, se, sd);
    unsigned myx[2], myy[2];
    if (!hi) {
        unsigned base = (unsigned)pr * 64u + (unsigned)(lane * 2);
#pragma unroll
        for (int vv = 0; vv < 2; vv++) {
            unsigned k0 = vv ? f20 : f10, k1 = vv ? f21 : f11;
            unsigned a0, a1, b0, b1;
            tf2x32(k0, k1, base, base + HALFC, a0, a1);
            tf2x32(k0, k1, base + 1u, base + 1u + HALFC, b0, b1);
            myx[vv] = a0; myy[vv] = b0;
            shn[vv][sub][lane][0] = a1;
            shn[vv][sub][lane][1] = b1;
        }
    }
    __syncthreads();
    if (hi) {
#pragma unroll
        for (int vv = 0; vv < 2; vv++) {
            myx[vv] = shn[vv][sub][lane][0];
            myy[vv] = shn[vv][sub][lane][1];
        }
    }
    ((float2*)(g_e2 + (row << 6)))[lane] = se;
    // pre-noise view values: y2pre = se + sd(view parts); noise sign from y2pre
    float y1x = se.x + sd.x, y1y = se.y + sd.y;   // view 1
    float y2x = se.x + sd.z, y2y = se.y + sd.w;   // view 2
    {
        float nx = u32_to_unit(myx[0]), ny = u32_to_unit(myy[0]);
        float sc = EPSC * rsqrtf(wredsum(nx * nx + ny * ny));
        sd.x += sgn(y1x) * nx * sc;
        sd.y += sgn(y1y) * ny * sc;
    }
    {
        float nx = u32_to_unit(myx[1]), ny = u32_to_unit(myy[1]);
        float sc = EPSC * rsqrtf(wredsum(nx * nx + ny * ny));
        sd.z += sgn(y2x) * nx * sc;
        sd.w += sgn(y2y) * ny * sc;
    }
    g_d2[(row << 5) + lane] = pack4h(sd.x, sd.y, sd.z, sd.w);
}

// ---------------- BPR: warp per batch entry, layer-3 rows on the fly ----------------
__global__ void __launch_bounds__(256) k_bpr(const int* __restrict__ ul,
                                             const int* __restrict__ pl,
                                             const int* __restrict__ nl) {
    int w = (blockIdx.x * blockDim.x + threadIdx.x) >> 5;
    int lane = threadIdx.x & 31;
    if (w >= BATCHC) return;
    const float third = 1.f / 3.f;
    int ru = ul[w];
    int rp = N_USERS + pl[w];
    int rn = N_USERS + nl[w];
    float2 u3 = csr_row(g_e2, ru, lane);
    float2 p3 = csr_row(g_e2, rp, lane);
    float2 n3 = csr_row(g_e2, rn, lane);
    float2 u1 = ((const float2*)(g_e1 + (ru << 6)))[lane];
    float2 u2 = ((const float2*)(g_e2 + (ru << 6)))[lane];
    float2 p1 = ((const float2*)(g_e1 + (rp << 6)))[lane];
    float2 p2 = ((const float2*)(g_e2 + (rp << 6)))[lane];
    float2 n1 = ((const float2*)(g_e1 + (rn << 6)))[lane];
    float2 n2 = ((const float2*)(g_e2 + (rn << 6)))[lane];
    float ux = (u1.x + u2.x + u3.x) * third, uy = (u1.y + u2.y + u3.y) * third;
    float px = (p1.x + p2.x + p3.x) * third, py = (p1.y + p2.y + p3.y) * third;
    float nx = (n1.x + n2.x + n3.x) * third, ny = (n1.y + n2.y + n3.y) * third;
    float pos = wredsum(ux * px + uy * py);
    float neg = wredsum(ux * nx + uy * ny);
    float ssu = wredsum(ux * ux + uy * uy);
    float ssp = wredsum(px * px + py * py);
    if (lane == 0) {
        float d = pos - neg;
        float sig = 1.f / (1.f + expf(-d));
        atomicAdd(&g_acc[0], -logf(1e-7f + sig));
        atomicAdd(&g_acc[1], ssu);
        atomicAdd(&g_acc[2], ssp);
    }
}

// ---------------- order-free unique (both lists in one launch) ----------------
__global__ void k_unique2(const int* __restrict__ ul, const int* __restrict__ pl) {
    int i = blockIdx.x * blockDim.x + threadIdx.x;
    if (i >= 2 * BATCHC) return;
    int which = (i >= BATCHC);
    int j = which ? i - BATCHC : i;
    int v = which ? pl[j] : ul[j];
    int fidx = which ? (N_USERS + v) : v;
    if (atomicExch(&g_flags[fidx], 1) == 0) {
        int p = atomicAdd(which ? &g_icnt : &g_ucnt, 1);
        (which ? g_iidx : g_uidx)[p] = v;
    }
}

// ---------------- finalize both views: layer-3 + noise + normalize + pos ----------------
__global__ void __launch_bounds__(256) k_vfinal(unsigned f10, unsigned f11,
                                                unsigned f20, unsigned f21) {
    int w = (blockIdx.x * blockDim.x + threadIdx.x) >> 5;
    int lane = threadIdx.x & 31;
    if (w >= 2 * BATCHC) return;
    int isItem = (w >= BATCHC);
    int j = isItem ? w - BATCHC : w;
    int cnt = isItem ? g_icnt : g_ucnt;
    if (j >= cnt) return;
    int row = isItem ? (N_USERS + g_iidx[j]) : g_uidx[j];
    float4 a3 = csr_row_l3(row, lane);
    float nx, ny, sc;
    row_noise(row, lane, f10, f11, nx, ny, sc);
    a3.x += sgn(a3.x) * nx * sc;
    a3.y += sgn(a3.y) * ny * sc;
    row_noise(row, lane, f20, f21, nx, ny, sc);
    a3.z += sgn(a3.z) * nx * sc;
    a3.w += sgn(a3.w) * ny * sc;
    // reconstruct y1, y2 from e + delta
    float2 e1r = ((const float2*)(g_e1 + (row << 6)))[lane];
    float2 e2r = ((const float2*)(g_e2 + (row << 6)))[lane];
    float4 d1r = unpack4h(g_d1[(row << 5) + lane]);
    float4 d2r = unpack4h(g_d2[(row << 5) + lane]);
    float s1x = (e1r.x + d1r.x) + (e2r.x + d2r.x) + a3.x;
    float s1y = (e1r.y + d1r.y) + (e2r.y + d2r.y) + a3.y;
    float inv1 = rsqrtf(wredsum(s1x * s1x + s1y * s1y));
    s1x *= inv1; s1y *= inv1;
    float s2x = (e1r.x + d1r.z) + (e2r.x + d2r.z) + a3.z;
    float s2y = (e1r.y + d1r.w) + (e2r.y + d2r.w) + a3.w;
    float inv2 = rsqrtf(wredsum(s2x * s2x + s2y * s2y));
    s2x *= inv2; s2y *= inv2;
    float* d1 = isItem ? g_V1i : g_V1u;
    float* d2 = isItem ? g_V2i : g_V2u;
    ((float2*)(d1 + (j << 6)))[lane] = make_float2(s1x, s1y);
    ((float2*)(d2 + (j << 6)))[lane] = make_float2(s2x, s2y);
    float d = wredsum(s2x * s1x + s2y * s1y);
    if (lane == 0) (isItem ? g_posI : g_posU)[j] = d * INV_TEMP;
}

// ---------------- InfoNCE (both halves via grid.z) ----------------
#define NCE_CSPLIT 16
#define NCE_COLS (BATCHC / NCE_CSPLIT)
__global__ void __launch_bounds__(128) k_nce() {
    int which = blockIdx.z;
    const float* __restrict__ V1 = which ? g_V1i : g_V1u;
    const float* __restrict__ V2 = which ? g_V2i : g_V2u;
    float* __restrict__ S = g_S + which * BATCHC;
    int U = which ? g_icnt : g_ucnt;
    int r = blockIdx.x * 128 + threadIdx.x;
    float4 v[16];
    if (r < U) {
        const float4* p = (const float4*)(V1 + (r << 6));
#pragma unroll
        for (int i = 0; i < 16; i++) v[i] = p[i];
    }
    __shared__ float sh[128 * DIM];
    float s = 0.f;
    int cbegin = blockIdx.y * NCE_COLS;
    for (int t = cbegin; t < cbegin + NCE_COLS; t += 128) {
        int cmax = U - t; if (cmax > 128) cmax = 128;
        if (cmax > 0) {
            const float4* src = (const float4*)(V2 + (t << 6));
            float4* d4 = (float4*)sh;
            for (int idx = threadIdx.x; idx < cmax * 16; idx += 128) d4[idx] = src[idx];
        }
        __syncthreads();
        if (r < U && cmax > 0) {
            for (int cc = 0; cc < cmax; cc++) {
                const float4* q = (const float4*)(sh + cc * DIM);
                float d0 = 0.f, d1 = 0.f, d2 = 0.f, d3 = 0.f;
#pragma unroll
                for (int i = 0; i < 16; i += 4) {
                    float4 q0 = q[i], q1 = q[i+1], q2 = q[i+2], q3 = q[i+3];
                    d0 = fmaf(v[i].x, q0.x, fmaf(v[i].y, q0.y, fmaf(v[i].z, q0.z, fmaf(v[i].w, q0.w, d0))));
                    d1 = fmaf(v[i+1].x, q1.x, fmaf(v[i+1].y, q1.y, fmaf(v[i+1].z, q1.z, fmaf(v[i+1].w, q1.w, d1))));
                    d2 = fmaf(v[i+2].x, q2.x, fmaf(v[i+2].y, q2.y, fmaf(v[i+2].z, q2.z, fmaf(v[i+2].w, q2.w, d2))));
                    d3 = fmaf(v[i+3].x, q3.x, fmaf(v[i+3].y, q3.y, fmaf(v[i+3].z, q3.z, fmaf(v[i+3].w, q3.w, d3))));
                }
                float dot = (d0 + d1) + (d2 + d3);
                s += __expf(dot * INV_TEMP - 5.0f);
            }
        }
        __syncthreads();
    }
    if (r < U && s != 0.f) atomicAdd(&S[r], s);
}

__global__ void __launch_bounds__(256) k_ncefin() {
    int i = blockIdx.x * blockDim.x + threadIdx.x;
    int which = (i >= BATCHC);
    int j = i - which * BATCHC;
    int U = which ? g_icnt : g_ucnt;
    float c = 0.f;
    if (i < 2 * BATCHC && j < U)
        c = 5.0f + logf(g_S[i]) - (which ? g_posI[j] : g_posU[j]);
    c = wredsum(c);
    if ((threadIdx.x & 31) == 0 && c != 0.f)
        atomicAdd(&g_acc[3 + which], c);
}

__global__ void k_final(float* out) {
    if (threadIdx.x == 0) {
        float rec = g_acc[0] / (float)BATCHC;
        float reg = 1e-4f * (sqrtf(g_acc[1]) + sqrtf(g_acc[2]));
        float cl = 0.2f * (g_acc[3] / (float)g_ucnt + g_acc[4] / (float)g_icnt);
        out[0] = rec + reg + cl;
        out[1] = cl;
    }
}

// ---------------- launch ----------------
extern "C" void kernel_launch(void* const* d_in, const int* in_sizes, int n_in,
                              void* d_out, int out_size) {
    const float* ue = (const float*)d_in[0];
    const float* ie = (const float*)d_in[1];
    const float* av = (const float*)d_in[2];
    const int*   ar = (const int*)d_in[3];
    const int*   ac = (const int*)d_in[4];
    const int*   ul = (const int*)d_in[5];
    const int*   pl = (const int*)d_in[6];
    const int*   nl = (const int*)d_in[7];
    float* out = (float*)d_out;

    const int SCAN_BLOCKS = (N_NODESC + 1023) / 1024;
    const int PAIRED_BLOCKS = NPAIR / 4;   // 18750: 4 row-pairs per 8-warp block

    unsigned seeds[2] = {101u, 202u};
    unsigned fk[2][3][2];
    for (int vv = 0; vv < 2; vv++)
        for (int k = 0; k < 3; k++)
            tf2x32(0u, seeds[vv], 0u, (unsigned)k, fk[vv][k][0], fk[vv][k][1]);

    k_init<<<(N_NODESC + 255) / 256, 256>>>();
    k_hist<<<(NNZC + 255) / 256, 256>>>(ar);
    k_scan1<<<SCAN_BLOCKS, 1024>>>();
    k_scan2<<<1, 256>>>(SCAN_BLOCKS);
    k_scan3<<<SCAN_BLOCKS, 1024>>>();
    k_fill<<<(NNZC + 255) / 256, 256>>>(ar, ac, av);
    k_unique2<<<(2 * BATCHC + 255) / 256, 256>>>(ul, pl);

    // layer 1: e1 + fp16 noise deltas (paired tf)
    k_spmm_e1_noise<<<PAIRED_BLOCKS, 256>>>(ue, ie,
        fk[0][0][0], fk[0][0][1], fk[1][0][0], fk[1][0][1]);
    // layer 2: e2 = A*e1 and d2 = A*d1 + noise2, L2-resident gathers
    k_spmm_l2<<<PAIRED_BLOCKS, 256>>>(fk[0][1][0], fk[0][1][1], fk[1][1][0], fk[1][1][1]);
    k_bpr<<<(BATCHC * 32) / 256, 256>>>(ul, pl, nl);
    k_vfinal<<<(2 * BATCHC * 32) / 256, 256>>>(fk[0][2][0], fk[0][2][1], fk[1][2][0], fk[1][2][1]);

    dim3 nce_grid(BATCHC / 128, NCE_CSPLIT, 2);
    k_nce<<<nce_grid, 128>>>();
    k_ncefin<<<(2 * BATCHC + 255) / 256, 256>>>();
    k_final<<<1, 32>>>(out);
}